// round 4
// baseline (speedup 1.0000x reference)
#include <cuda_runtime.h>
#include <cstdint>

#define B    16
#define C    37
#define H    224
#define W    224
#define HW   (H*W)          // 50176

// ---------------- scratch (device globals: no allocation allowed) -----------
__device__ unsigned char g_lab[B * HW];   // argmax index per pixel (0..36)
__device__ int           g_maxv[B];       // per-image max of lab
__device__ unsigned char g_open[B * HW];  // mask after opening

// ---------------- K0: reset per-image max --------------------------------
__global__ void k0_init() {
    if (threadIdx.x < B) g_maxv[threadIdx.x] = 0;
}

// ---------------- K1: argmax over channels + per-image max ----------------
// 4 pixels per thread via float4. grid = (HW/4/256, B)
__global__ void k1_argmax(const float* __restrict__ in) {
    const int b  = blockIdx.y;
    const int q4 = blockIdx.x * blockDim.x + threadIdx.x;   // 0..12543
    const float4* base = reinterpret_cast<const float4*>(in) +
                         (size_t)b * C * (HW / 4) + q4;

    float4 v = base[0];
    float bx = v.x, by = v.y, bz = v.z, bw = v.w;
    int   ix = 0,  iy = 0,  iz = 0,  iw = 0;
    #pragma unroll
    for (int c = 1; c < C; ++c) {
        float4 u = base[(size_t)c * (HW / 4)];
        if (u.x > bx) { bx = u.x; ix = c; }
        if (u.y > by) { by = u.y; iy = c; }
        if (u.z > bz) { bz = u.z; iz = c; }
        if (u.w > bw) { bw = u.w; iw = c; }
    }
    uchar4 o;
    o.x = (unsigned char)ix; o.y = (unsigned char)iy;
    o.z = (unsigned char)iz; o.w = (unsigned char)iw;
    reinterpret_cast<uchar4*>(g_lab + (size_t)b * HW)[q4] = o;

    // per-image max of lab
    int m = max(max(ix, iy), max(iz, iw));
    unsigned wm = __reduce_max_sync(0xffffffffu, (unsigned)m);
    __shared__ int wmax[8];
    int lane = threadIdx.x & 31, wid = threadIdx.x >> 5;
    if (lane == 0) wmax[wid] = (int)wm;
    __syncthreads();
    if (threadIdx.x == 0) {
        int mm = wmax[0];
        #pragma unroll
        for (int i = 1; i < 8; ++i) mm = max(mm, wmax[i]);
        atomicMax(&g_maxv[b], mm);
    }
}

// ---------------- K2: quantize -> blur -> threshold -> open ---------------
// One CTA per 32x32 tile, halo 4 (blur r2 + erode r1 + dilate r1).
// grid = (7, 7, B), 256 threads.
__device__ __forceinline__ int refl(int i) {
    // BORDER_REFLECT_101 on [0, 223]
    i = (i < 0) ? -i : i;
    return (i > 223) ? (446 - i) : i;
}

__global__ void k2_open() {
    __shared__ unsigned char sq[40][48];   // q with reflect-101, global (y0-4.., x0-4..)
    __shared__ unsigned char smm[36][40];  // m (blur>128), global (y0-2.., x0-2..)
    __shared__ unsigned char se[34][36];   // eroded,       global (y0-1.., x0-1..)

    const int b  = blockIdx.z;
    const int y0 = blockIdx.y * 32;
    const int x0 = blockIdx.x * 32;
    const int t  = threadIdx.x;
    const int mv = g_maxv[b];
    const unsigned char* lab = g_lab + (size_t)b * HW;

    // load 40x40 quantized tile with reflect-101 (matches blur padding)
    for (int i = t; i < 1600; i += 256) {
        int ly = i / 40, lx = i - ly * 40;
        int gy = refl(y0 - 4 + ly);
        int gx = refl(x0 - 4 + lx);
        int l  = lab[gy * 224 + gx];
        sq[ly][lx] = (mv > 0) ? (unsigned char)((255 * l) / mv) : 0;
    }
    __syncthreads();

    // 5x5 integer blur, threshold S>128  (== round(S/256) > 0)
    const int Wt[5] = {1, 4, 6, 4, 1};
    for (int i = t; i < 1296; i += 256) {
        int my = i / 36, mx = i - my * 36;
        int S = 0;
        #pragma unroll
        for (int ii = 0; ii < 5; ++ii) {
            int rs = 0;
            #pragma unroll
            for (int jj = 0; jj < 5; ++jj) rs += Wt[jj] * (int)sq[my + ii][mx + jj];
            S += Wt[ii] * rs;
        }
        smm[my][mx] = (S > 128) ? 1 : 0;
    }
    __syncthreads();

    // erode (cross, out-of-image == True)
    for (int i = t; i < 1156; i += 256) {
        int ey = i / 34, ex = i - ey * 34;
        int gy = y0 - 1 + ey, gx = x0 - 1 + ex;
        bool v = smm[ey + 1][ex + 1];
        v = v && ((gy - 1 < 0)    || smm[ey][ex + 1]);
        v = v && ((gy + 1 > 223)  || smm[ey + 2][ex + 1]);
        v = v && ((gx - 1 < 0)    || smm[ey + 1][ex]);
        v = v && ((gx + 1 > 223)  || smm[ey + 1][ex + 2]);
        se[ey][ex] = v ? 1 : 0;
    }
    __syncthreads();

    // dilate (cross, out-of-image == False), write opened mask
    for (int i = t; i < 1024; i += 256) {
        int oy = i >> 5, ox = i & 31;
        int gy = y0 + oy, gx = x0 + ox;
        bool v = se[oy + 1][ox + 1];
        v = v || ((gy - 1 >= 0)  && se[oy][ox + 1]);
        v = v || ((gy + 1 < 224) && se[oy + 2][ox + 1]);
        v = v || ((gx - 1 >= 0)  && se[oy + 1][ox]);
        v = v || ((gx + 1 < 224) && se[oy + 1][ox + 2]);
        g_open[(size_t)b * HW + gy * 224 + gx] = v ? 1 : 0;
    }
}

// ---------------- K3: border flood fill of background + output ------------
// One CTA per image. comp/seed byte arrays in dynamic smem (2*HW = 100352 B).
// In-place monotone propagation to a unique fixpoint -> deterministic.
__global__ void __launch_bounds__(1024) k3_fill(float* __restrict__ out) {
    extern __shared__ unsigned char sh[];
    unsigned char* comp = sh;          // !opened mask
    unsigned char* seed = sh + HW;     // flooded background
    __shared__ int s_changed;

    const int b = blockIdx.x;
    const int t = threadIdx.x;
    const unsigned char* mo = g_open + (size_t)b * HW;

    for (int i = t; i < HW; i += 1024) {
        unsigned char c = mo[i] ? 0 : 1;
        comp[i] = c;
        int y = i / 224, x = i - y * 224;
        seed[i] = (c && (y == 0 || y == 223 || x == 0 || x == 223)) ? 1 : 0;
    }
    __syncthreads();

    volatile unsigned char* vs = seed;
    while (true) {
        if (t == 0) s_changed = 0;
        __syncthreads();
        int ch = 0;
        for (int i = t; i < HW; i += 1024) {
            if (comp[i] && !vs[i]) {
                int y = i / 224, x = i - y * 224;
                bool nb = (y > 0   && vs[i - 224]) || (y < 223 && vs[i + 224]) ||
                          (x > 0   && vs[i - 1])   || (x < 223 && vs[i + 1]);
                if (nb) { vs[i] = 1; ch = 1; }
            }
        }
        if (ch) s_changed = 1;
        __syncthreads();
        if (!s_changed) break;
        __syncthreads();   // protect s_changed read before next reset
    }

    // mask = !background ; replicate to 3 channels, float32, float4 stores
    float* ob = out + (size_t)b * 3 * HW;
    const uchar4* s4p = reinterpret_cast<const uchar4*>(seed);
    for (int i = t; i < HW / 4; i += 1024) {
        uchar4 s4 = s4p[i];
        float4 v;
        v.x = s4.x ? 0.f : 1.f;
        v.y = s4.y ? 0.f : 1.f;
        v.z = s4.z ? 0.f : 1.f;
        v.w = s4.w ? 0.f : 1.f;
        reinterpret_cast<float4*>(ob)[i]          = v;
        reinterpret_cast<float4*>(ob + HW)[i]     = v;
        reinterpret_cast<float4*>(ob + 2 * HW)[i] = v;
    }
}

// ---------------- launch ---------------------------------------------------
extern "C" void kernel_launch(void* const* d_in, const int* in_sizes, int n_in,
                              void* d_out, int out_size) {
    const float* in  = (const float*)d_in[0];
    float*       out = (float*)d_out;

    // k3 needs >48KB dynamic smem; setting the attribute is idempotent and
    // executes immediately (not a stream op), so it is graph-capture safe.
    cudaFuncSetAttribute(k3_fill, cudaFuncAttributeMaxDynamicSharedMemorySize,
                         2 * HW);

    k0_init<<<1, 32>>>();

    dim3 g1(HW / 4 / 256, B);          // (49, 16)
    k1_argmax<<<g1, 256>>>(in);

    dim3 g2(7, 7, B);
    k2_open<<<g2, 256>>>();

    k3_fill<<<B, 1024, 2 * HW>>>(out);
}